// round 1
// baseline (speedup 1.0000x reference)
#include <cuda_runtime.h>
#include <math.h>

// ---------------- problem constants ----------------
#define NN   2048
#define NT   512          // threads per block for row kernels
#define CPT  4            // elements per thread (NN/NT)
#define BB   8
#define KK   4
#define BK   32           // B*K
#define TWO_PI_F 6.283185307179586f

// output layout (flattened tuple, fp32)
#define OUT_EIF 0
#define OUT_XM  65536
#define OUT_YM  131072
#define OUT_BSX 196608
#define OUT_BSY 212992
#define OUT_LAM 229376
#define OUT_SC  245760

// ---------------- scratch (__device__ globals; no allocation allowed) ------
__device__ float g_scal[4];        // 0:new_alpha 1:new_beta 2:coefA=2/na 3:coefS=2/betathr
__device__ float g_u[BB*NN];
__device__ float g_cos[BK*NN];
__device__ float g_sin[BK*NN];
__device__ float g_rhsx[BK*NN];
__device__ float g_rhsy[BK*NN];
__device__ float g_xs[BK*NN];
__device__ float g_ys[BK*NN];

// ---------------- helpers ----------------
__device__ __forceinline__ float blockReduceSum(float v, volatile float* sred)
{
    __syncthreads();                       // protect sred reuse across calls
#pragma unroll
    for (int o = 16; o > 0; o >>= 1) v += __shfl_down_sync(0xffffffffu, v, o);
    int w = threadIdx.x >> 5;
    if ((threadIdx.x & 31) == 0) sred[w] = v;
    __syncthreads();
    if (threadIdx.x == 0) {
        float s = 0.f;
        for (int i = 0; i < (int)(blockDim.x >> 5); i++) s += sred[i];
        sred[0] = s;
    }
    __syncthreads();
    return sred[0];
}

// pentadiagonal stencil: y = (D^T D) p  where D is the path-Laplacian-like matrix.
// Exact integer coefficients: interior [1,-4,6,-4,1], rows 0/1/N-2/N-1 modified.
__device__ __forceinline__ float penta(const float* sp, int i)
{
    if (i >= 2 && i <= NN - 3) {
        return sp[i-2] - 4.f*sp[i-1] + 6.f*sp[i] - 4.f*sp[i+1] + sp[i+2];
    }
    if (i == 0)      return 2.f*sp[0] - 3.f*sp[1] + sp[2];
    if (i == 1)      return -3.f*sp[0] + 6.f*sp[1] - 4.f*sp[2] + sp[3];
    if (i == NN-2)   return sp[NN-4] - 4.f*sp[NN-3] + 6.f*sp[NN-2] - 3.f*sp[NN-1];
    /* i == NN-1 */  return sp[NN-3] - 3.f*sp[NN-2] + 2.f*sp[NN-1];
}

// Block-cooperative CG matching reference semantics exactly:
//   mv(p) = coef * (M p) + (diag + 1e-6) * p
//   a = rsold/(pAp+1e-12); x,r frozen by `done`; p,rsold frozen by `done1`;
//   done1 = done | (sqrt(rsnew) < 1e-6); 30 iterations.
// Precondition: caller placed x0 into sp[] and synced. d[] already includes +1e-6.
__device__ void cg_block(float coef, const float d[CPT], const float rhs[CPT],
                         float x[CPT], float* sp, volatile float* sred)
{
    const int tid = threadIdx.x;
    float r[CPT];
    float rs_loc = 0.f;
#pragma unroll
    for (int c = 0; c < CPT; c++) {
        int i = tid + c * NT;
        float Ax = coef * penta(sp, i) + d[c] * sp[i];
        r[c] = rhs[c] - Ax;
        rs_loc += r[c] * r[c];
    }
    float rsold = blockReduceSum(rs_loc, sred);
    __syncthreads();
#pragma unroll
    for (int c = 0; c < CPT; c++) sp[tid + c * NT] = r[c];   // p = r
    __syncthreads();

    bool done = false;
    for (int it = 0; it < 30; it++) {
        float Ap[CPT], pr[CPT];
        float pAp_loc = 0.f;
#pragma unroll
        for (int c = 0; c < CPT; c++) {
            int i = tid + c * NT;
            pr[c] = sp[i];
            Ap[c] = coef * penta(sp, i) + d[c] * pr[c];
            pAp_loc += pr[c] * Ap[c];
        }
        float pAp = blockReduceSum(pAp_loc, sred);
        float a = rsold / (pAp + 1e-12f);
        if (!done) {
#pragma unroll
            for (int c = 0; c < CPT; c++) { x[c] += a * pr[c]; r[c] -= a * Ap[c]; }
        }
        float rsn_loc = 0.f;
#pragma unroll
        for (int c = 0; c < CPT; c++) rsn_loc += r[c] * r[c];
        float rsnew = blockReduceSum(rsn_loc, sred);
        bool done1 = done || (sqrtf(rsnew) < 1e-6f);
        float bta = rsnew / (rsold + 1e-12f);
        __syncthreads();                     // all penta reads of sp are done
        if (!done1) {
#pragma unroll
            for (int c = 0; c < CPT; c++) sp[tid + c * NT] = r[c] + bta * pr[c];
            rsold = rsnew;
        }
        done = done1;
        __syncthreads();
    }
}

// cumtrapz-based phase: each thread owns a contiguous chunk of 4.
// Returns phase values for its chunk in ph4[0..3] (= 2*pi*cumtrapz(y, dx)).
__device__ void phase_scan_chunk(const float* __restrict__ y, float halfdx,
                                 float* spart, float ph4[CPT])
{
    int tid = threadIdx.x;
    int base = tid * CPT;
    float4 y4 = *reinterpret_cast<const float4*>(y + base);
    float a0 = (base > 0) ? (y[base-1] + y4.x) * halfdx : 0.f;
    float a1 = (y4.x + y4.y) * halfdx;
    float a2 = (y4.y + y4.z) * halfdx;
    float a3 = (y4.z + y4.w) * halfdx;
    float s0 = a0, s1 = s0 + a1, s2 = s1 + a2, s3 = s2 + a3;
    spart[tid] = s3;
    __syncthreads();
    for (int off = 1; off < NT; off <<= 1) {
        float v   = spart[tid];
        float add = (tid >= off) ? spart[tid - off] : 0.f;
        __syncthreads();
        spart[tid] = v + add;
        __syncthreads();
    }
    float offv = (tid > 0) ? spart[tid - 1] : 0.f;
    ph4[0] = TWO_PI_F * (offv + s0);
    ph4[1] = TWO_PI_F * (offv + s1);
    ph4[2] = TWO_PI_F * (offv + s2);
    ph4[3] = TWO_PI_F * (offv + s3);
}

// ---------------- K1: hyperparameter-refinement MLP (scalars) -------------
__global__ void mlp_kernel(const float* __restrict__ init_freqs,
                           const float* __restrict__ alpha_p,
                           const float* __restrict__ beta_p,
                           const int*   __restrict__ iter_p,
                           const float* __restrict__ fe_w1, const float* __restrict__ fe_b1,
                           const float* __restrict__ fe_w2, const float* __restrict__ fe_b2,
                           const float* __restrict__ pr_w1, const float* __restrict__ pr_b1,
                           const float* __restrict__ pr_w2, const float* __restrict__ pr_b2,
                           const float* __restrict__ pr_w3, const float* __restrict__ pr_b3,
                           const float* __restrict__ iw_p,
                           float* __restrict__ d_out)
{
    __shared__ float avg[BB];
    __shared__ float h1[BB*32];
    __shared__ float z0[BB*18];   // h2 (16) + alpha + beta
    __shared__ float z1[BB*64];
    __shared__ float z2[BB*32];
    __shared__ float res[BB*2];
    int tid = threadIdx.x;
    float alpha = *alpha_p, beta = *beta_p;

    if (tid < BB) {
        const float* f = init_freqs + tid * KK;
        avg[tid] = (((f[0] + f[1]) + f[2]) + f[3]) * 0.25f;
    }
    __syncthreads();
    {   // layer fe1: (B,1)->(B,32)
        int b = tid >> 5, j = tid & 31;
        h1[b*32 + j] = fmaxf(0.f, avg[b] * fe_w1[j] + fe_b1[j]);
    }
    __syncthreads();
    if (tid < 128) { // fe2: (B,32)->(B,16)
        int b = tid >> 4, j = tid & 15;
        float s = fe_b2[j];
        for (int e = 0; e < 32; e++) s += h1[b*32 + e] * fe_w2[j*32 + e];
        z0[b*18 + j] = fmaxf(0.f, s);
    }
    if (tid < BB) { z0[tid*18 + 16] = alpha; z0[tid*18 + 17] = beta; }
    __syncthreads();
    for (int o = 0; o < 2; o++) { // pr1: (B,18)->(B,64)
        int idx = tid + o * 256;
        int b = idx >> 6, j = idx & 63;
        float s = pr_b1[j];
        for (int e = 0; e < 18; e++) s += z0[b*18 + e] * pr_w1[j*18 + e];
        z1[b*64 + j] = fmaxf(0.f, s);
    }
    __syncthreads();
    {   // pr2: (B,64)->(B,32)
        int b = tid >> 5, j = tid & 31;
        float s = pr_b2[j];
        for (int e = 0; e < 64; e++) s += z1[b*64 + e] * pr_w2[j*64 + e];
        z2[b*32 + j] = fmaxf(0.f, s);
    }
    __syncthreads();
    if (tid < 16) { // pr3: (B,32)->(B,2), tanh
        int b = tid >> 1, j = tid & 1;
        float s = pr_b3[j];
        for (int e = 0; e < 32; e++) s += z2[b*32 + e] * pr_w3[j*32 + e];
        res[b*2 + j] = tanhf(s);
    }
    __syncthreads();
    if (tid == 0) {
        float iw = *iw_p;
        int it = *iter_p;
        float fac = 1.f / (1.f + expf(-iw * (float)it));
        float m0 = 0.f, m1 = 0.f;
        for (int b = 0; b < BB; b++) {
            m0 += (res[b*2 + 0] * fac * 0.1f) * alpha;
            m1 += (res[b*2 + 1] * fac * 0.1f) * beta;
        }
        m0 *= 0.125f; m1 *= 0.125f;
        float na = fminf(fmaxf(alpha + m0, 1e-6f), 0.01f);
        float nb = fminf(fmaxf(beta  + m1, 1e-6f), 0.1f);
        double bt = pow(10.0, (double)it / 36.0 - 10.0);
        float betathr = fminf((float)bt, nb);
        g_scal[0] = na;
        g_scal[1] = nb;
        g_scal[2] = 2.f / na;
        g_scal[3] = 2.f / betathr;
        d_out[OUT_SC + 0] = na;
        d_out[OUT_SC + 1] = nb;
    }
}

// ---------------- K2: u = projec5(s - sum_x - sum_y - lamuda/na, var) -----
__global__ __launch_bounds__(NT) void u_kernel(const float* __restrict__ s,
                                               const float* __restrict__ sumx,
                                               const float* __restrict__ sumy,
                                               const float* __restrict__ lam,
                                               const float* __restrict__ var_p)
{
    __shared__ float sred[32];
    int b = blockIdx.x, tid = threadIdx.x;
    float na = g_scal[0];
    int base = b * NN + tid * CPT;
    float4 sv  = *reinterpret_cast<const float4*>(s    + base);
    float4 sx  = *reinterpret_cast<const float4*>(sumx + base);
    float4 sy  = *reinterpret_cast<const float4*>(sumy + base);
    float4 lv  = *reinterpret_cast<const float4*>(lam  + base);
    float v[CPT];
    v[0] = sv.x - sx.x - sy.x - lv.x / na;
    v[1] = sv.y - sx.y - sy.y - lv.y / na;
    v[2] = sv.z - sx.z - sy.z - lv.z / na;
    v[3] = sv.w - sx.w - sy.w - lv.w / na;
    float loc = v[0]*v[0] + v[1]*v[1] + v[2]*v[2] + v[3]*v[3];
    float n2 = blockReduceSum(loc, sred);
    float n = sqrtf(n2);
    float e = sqrtf((float)NN * (*var_p));
    float scale = (n > e) ? (e / fmaxf(n, 1e-30f)) : 1.f;
#pragma unroll
    for (int c = 0; c < CPT; c++) g_u[base + c] = v[c] * scale;
}

// ---------------- K3: phase, cos/sin, rhs_x, rhs_y ------------------------
__global__ __launch_bounds__(NT) void rhs_kernel(const float* __restrict__ s,
                                                 const float* __restrict__ eIF,
                                                 const float* __restrict__ xm,
                                                 const float* __restrict__ ym,
                                                 const float* __restrict__ sumx,
                                                 const float* __restrict__ sumy,
                                                 const float* __restrict__ lam,
                                                 const float* __restrict__ fs_p)
{
    __shared__ float spart[NT];
    int bk = blockIdx.x;
    int b = bk >> 2;
    int tid = threadIdx.x;
    float na = g_scal[0];
    float dxf = 1.0f / (*fs_p);
    float halfdx = 0.5f * dxf;

    float ph4[CPT];
    phase_scan_chunk(eIF + bk * NN, halfdx, spart, ph4);

    int rbase = bk * NN + tid * CPT;
    int bbase = b * NN + tid * CPT;
#pragma unroll
    for (int c = 0; c < CPT; c++) {
        double sd, cd;
        sincos((double)ph4[c], &sd, &cd);
        float cc = (float)cd, ss = (float)sd;
        float xv = xm[rbase + c], yv = ym[rbase + c];
        float resid = s[bbase + c]
                    - (sumx[bbase + c] - xv * cc)
                    - (sumy[bbase + c] - yv * ss)
                    - g_u[bbase + c]
                    - lam[bbase + c] / na;
        g_cos[rbase + c] = cc;
        g_sin[rbase + c] = ss;
        g_rhsx[rbase + c] = cc * resid;
        g_rhsy[rbase + c] = ss * resid;
    }
}

// ---------------- K4: CG solves for xs (which=0) and ys (which=1) ---------
__global__ __launch_bounds__(NT) void cg_xy_kernel(const float* __restrict__ xm,
                                                   const float* __restrict__ ym)
{
    __shared__ float sp[NN];
    __shared__ float sred[32];
    int id = blockIdx.x;
    int which = id >> 5;
    int bk = id & 31;
    int tid = threadIdx.x;
    const float* cs  = (which ? g_sin  : g_cos)  + bk * NN;
    const float* rh  = (which ? g_rhsy : g_rhsx) + bk * NN;
    const float* x0p = (which ? ym     : xm)     + bk * NN;
    float*       outp= (which ? g_ys   : g_xs)   + bk * NN;
    float coef = g_scal[2];

    float d[CPT], rhs[CPT], x[CPT];
#pragma unroll
    for (int c = 0; c < CPT; c++) {
        int i = tid + c * NT;
        float cc = cs[i];
        d[c] = cc * cc + 1e-6f;
        rhs[c] = rh[i];
        x[c] = x0p[i];
        sp[i] = x[c];
    }
    __syncthreads();
    cg_block(coef, d, rhs, x, sp, sred);
#pragma unroll
    for (int c = 0; c < CPT; c++) outp[tid + c * NT] = x[c];
}

// ---------------- K5: deltaIF + smooth CG + write eIF/xm/ym outputs -------
__global__ __launch_bounds__(NT) void smooth_kernel(const float* __restrict__ eIF,
                                                    const float* __restrict__ xm,
                                                    const float* __restrict__ ym,
                                                    const int*   __restrict__ mask,
                                                    const float* __restrict__ fs_p,
                                                    float* __restrict__ d_out)
{
    __shared__ float sp[NN];
    __shared__ float sred[32];
    int bk = blockIdx.x;
    int tid = threadIdx.x;
    float dxf = 1.0f / (*fs_p);
    const float* xr = g_xs + bk * NN;
    const float* yr = g_ys + bk * NN;

    float rhs[CPT], d[CPT], x[CPT];
#pragma unroll
    for (int c = 0; c < CPT; c++) {
        int i = tid + c * NT;
        float xb, yb;
        if (i == 0) {
            xb = (xr[1] - xr[0]) / dxf;
            yb = (yr[1] - yr[0]) / dxf;
        } else if (i == NN - 1) {
            xb = (xr[NN-1] - xr[NN-2]) / dxf;
            yb = (yr[NN-1] - yr[NN-2]) / dxf;
        } else {
            xb = (xr[i+1] - xr[i-1]) / (2.0f * dxf);
            yb = (yr[i+1] - yr[i-1]) / (2.0f * dxf);
        }
        float xv = xr[i], yv = yr[i];
        float denom = xv * xv + yv * yv + 1e-12f;
        rhs[c] = (xv * yb - yv * xb) / (denom * TWO_PI_F);
        d[c] = 1.0f + 1e-6f;
        x[c] = 0.f;
        sp[i] = 0.f;
    }
    __syncthreads();
    cg_block(g_scal[3], d, rhs, x, sp, sred);

    bool act = (mask[bk] != 0);
#pragma unroll
    for (int c = 0; c < CPT; c++) {
        int i = tid + c * NT;
        int gi = bk * NN + i;
        float e = eIF[gi];
        d_out[OUT_EIF + gi] = act ? (e - 0.5f * x[c]) : e;
        d_out[OUT_XM  + gi] = act ? xr[i] : xm[gi];
        d_out[OUT_YM  + gi] = act ? yr[i] : ym[gi];
    }
}

// ---------------- K6: reconstruct bsx/bsy + lamuda update -----------------
__global__ __launch_bounds__(NT) void final_kernel(const float* __restrict__ s,
                                                   const float* __restrict__ lam,
                                                   const int*   __restrict__ mask,
                                                   const float* __restrict__ fs_p,
                                                   float* __restrict__ d_out)
{
    __shared__ float spart[NT];
    int b = blockIdx.x;
    int tid = threadIdx.x;
    float na = g_scal[0];
    float halfdx = 0.5f * (1.0f / (*fs_p));

    float bsx[CPT] = {0.f, 0.f, 0.f, 0.f};
    float bsy[CPT] = {0.f, 0.f, 0.f, 0.f};

    for (int k = 0; k < KK; k++) {
        int bk = b * KK + k;
        const float* ne = d_out + OUT_EIF + bk * NN;
        float ph4[CPT];
        phase_scan_chunk(ne, halfdx, spart, ph4);
        float mf = (mask[bk] != 0) ? 1.f : 0.f;
        int rbase = bk * NN + tid * CPT;
#pragma unroll
        for (int c = 0; c < CPT; c++) {
            double sd, cd;
            sincos((double)ph4[c], &sd, &cd);
            bsx[c] += mf * d_out[OUT_XM + rbase + c] * (float)cd;
            bsy[c] += mf * d_out[OUT_YM + rbase + c] * (float)sd;
        }
        __syncthreads();  // spart reuse across k
    }
#pragma unroll
    for (int c = 0; c < CPT; c++) {
        int i = tid * CPT + c;
        int gi = b * NN + i;
        d_out[OUT_BSX + gi] = bsx[c];
        d_out[OUT_BSY + gi] = bsy[c];
        d_out[OUT_LAM + gi] = lam[gi] + na * (g_u[gi] + bsx[c] + bsy[c] - s[gi]);
    }
}

// ---------------- launch ---------------------------------------------------
extern "C" void kernel_launch(void* const* d_in, const int* in_sizes, int n_in,
                              void* d_out_v, int out_size)
{
    const float* s        = (const float*)d_in[0];
    const float* eIF      = (const float*)d_in[1];
    const float* xm       = (const float*)d_in[2];
    const float* ym       = (const float*)d_in[3];
    const float* sum_x    = (const float*)d_in[4];
    const float* sum_y    = (const float*)d_in[5];
    const float* lamuda   = (const float*)d_in[6];
    const float* initf    = (const float*)d_in[7];
    const int*   mmask    = (const int*)  d_in[8];
    const float* alpha    = (const float*)d_in[9];
    const float* beta     = (const float*)d_in[10];
    const float* var      = (const float*)d_in[11];
    const float* fs       = (const float*)d_in[12];
    const int*   iter     = (const int*)  d_in[13];
    const float* fe_w1    = (const float*)d_in[14];
    const float* fe_b1    = (const float*)d_in[15];
    const float* fe_w2    = (const float*)d_in[16];
    const float* fe_b2    = (const float*)d_in[17];
    const float* pr_w1    = (const float*)d_in[18];
    const float* pr_b1    = (const float*)d_in[19];
    const float* pr_w2    = (const float*)d_in[20];
    const float* pr_b2    = (const float*)d_in[21];
    const float* pr_w3    = (const float*)d_in[22];
    const float* pr_b3    = (const float*)d_in[23];
    const float* iw       = (const float*)d_in[24];
    float* d_out = (float*)d_out_v;

    mlp_kernel<<<1, 256>>>(initf, alpha, beta, iter,
                           fe_w1, fe_b1, fe_w2, fe_b2,
                           pr_w1, pr_b1, pr_w2, pr_b2, pr_w3, pr_b3,
                           iw, d_out);
    u_kernel<<<BB, NT>>>(s, sum_x, sum_y, lamuda, var);
    rhs_kernel<<<BK, NT>>>(s, eIF, xm, ym, sum_x, sum_y, lamuda, fs);
    cg_xy_kernel<<<2 * BK, NT>>>(xm, ym);
    smooth_kernel<<<BK, NT>>>(eIF, xm, ym, mmask, fs, d_out);
    final_kernel<<<BB, NT>>>(s, lamuda, mmask, fs, d_out);
}

// round 2
// speedup vs baseline: 1.6823x; 1.6823x over previous
#include <cuda_runtime.h>
#include <math.h>

// ---------------- problem constants ----------------
#define NN   2048
#define NT   512
#define BB   8
#define KK   4
#define BK   32
#define TWO_PI_F 6.283185307179586f

// output layout (flattened tuple, fp32)
#define OUT_EIF 0
#define OUT_XM  65536
#define OUT_YM  131072
#define OUT_BSX 196608
#define OUT_BSY 212992
#define OUT_LAM 229376
#define OUT_SC  245760

// ---------------- scratch (__device__ globals) ------
__device__ float g_scal[4];        // 0:new_alpha 1:new_beta 2:coefA 3:coefS
__device__ float g_u[BB*NN];
__device__ float g_cos[BK*NN];
__device__ float g_sin[BK*NN];
__device__ float g_rhsx[BK*NN];
__device__ float g_rhsy[BK*NN];
__device__ float g_xs[BK*NN];
__device__ float g_ys[BK*NN];

// ---------------- barrier helpers ----------------
template<int GSIZE>
__device__ __forceinline__ void barx(int barId)
{
    if (GSIZE == 512) __syncthreads();
    else asm volatile("bar.sync %0, %1;" :: "r"(barId), "r"(GSIZE) : "memory");
}

// group reduce: shuffle -> partials -> ONE barrier -> every thread sums partials
template<int GSIZE>
__device__ __forceinline__ float gred(float v, volatile float* sred, int gtid, int barId)
{
#pragma unroll
    for (int o = 16; o > 0; o >>= 1) v += __shfl_down_sync(0xffffffffu, v, o);
    if ((gtid & 31) == 0) sred[gtid >> 5] = v;
    barx<GSIZE>(barId);
    float s = 0.f;
#pragma unroll
    for (int j = 0; j < GSIZE / 32; j++) s += sred[j];
    return s;
}

// pentadiagonal stencil of (D^T D); window w[k] = sp[base-2+k], element i = base+c.
__device__ __forceinline__ float sten(const float* w, int c, int i)
{
    if (i == 0)        return 2.f*w[c+2] - 3.f*w[c+3] + w[c+4];
    if (i == 1)        return -3.f*w[c+1] + 6.f*w[c+2] - 4.f*w[c+3] + w[c+4];
    if (i == NN-2)     return w[c] - 4.f*w[c+1] + 6.f*w[c+2] - 3.f*w[c+3];
    if (i == NN-1)     return w[c] - 3.f*w[c+1] + 2.f*w[c+2];
    return w[c] - 4.f*w[c+1] + 6.f*w[c+2] - 4.f*w[c+3] + w[c+4];
}

// Block/group-cooperative CG matching reference semantics exactly.
// Precondition: caller wrote x0 into sp (entry barrier is inside).
template<int GSIZE, int NPT>
__device__ void cg_t(int gtid, int barId, float coef,
                     const float* d, const float* rhs, float* x,
                     float* sp, volatile float* sA, volatile float* sB)
{
    const int base = gtid * NPT;
    float r[NPT], w[NPT + 4];
    barx<GSIZE>(barId);                          // x0 visible

#pragma unroll
    for (int k = 0; k < NPT + 4; k++) { int idx = base - 2 + k; w[k] = (idx >= 0 && idx < NN) ? sp[idx] : 0.f; }
    float rl = 0.f;
#pragma unroll
    for (int c = 0; c < NPT; c++) {
        int i = base + c;
        float Ax = coef * sten(w, c, i) + d[c] * w[c+2];
        r[c] = rhs[c] - Ax;
        rl += r[c] * r[c];
    }
    float rsold = gred<GSIZE>(rl, sA, gtid, barId);
#pragma unroll
    for (int c = 0; c < NPT; c++) sp[base + c] = r[c];   // p = r
    barx<GSIZE>(barId);

    bool done = false;
    for (int it = 0; it < 30; it++) {
#pragma unroll
        for (int k = 0; k < NPT + 4; k++) { int idx = base - 2 + k; w[k] = (idx >= 0 && idx < NN) ? sp[idx] : 0.f; }
        float Ap[NPT];
        float pl = 0.f;
#pragma unroll
        for (int c = 0; c < NPT; c++) {
            int i = base + c;
            Ap[c] = coef * sten(w, c, i) + d[c] * w[c+2];
            pl += w[c+2] * Ap[c];
        }
        float pAp = gred<GSIZE>(pl, sA, gtid, barId);   // barrier also fences stencil reads
        float a = rsold / (pAp + 1e-12f);
        if (!done) {
#pragma unroll
            for (int c = 0; c < NPT; c++) { x[c] += a * w[c+2]; r[c] -= a * Ap[c]; }
        }
        float rl2 = 0.f;
#pragma unroll
        for (int c = 0; c < NPT; c++) rl2 += r[c] * r[c];
        float rsnew = gred<GSIZE>(rl2, sB, gtid, barId);
        bool done1 = done || (sqrtf(rsnew) < 1e-6f);
        float bta = rsnew / (rsold + 1e-12f);
        if (!done1) {
#pragma unroll
            for (int c = 0; c < NPT; c++) sp[base + c] = r[c] + bta * w[c+2];
            rsold = rsnew;
        }
        done = done1;
        barx<GSIZE>(barId);                      // p writes visible before next stencil
    }
}

// fast phase scan: 512 threads, 4 contiguous elems each; 2 barriers total.
__device__ __forceinline__ void fast_phase(const float* __restrict__ y, float halfdx,
                                           volatile float* wsum, float ph4[4])
{
    int tid = threadIdx.x;
    int lane = tid & 31, wi = tid >> 5;
    int base = tid * 4;
    float4 y4 = *reinterpret_cast<const float4*>(y + base);
    float a0 = 0.f;
    if (base > 0) a0 = (y[base - 1] + y4.x) * halfdx;
    float s0 = a0;
    float s1 = s0 + (y4.x + y4.y) * halfdx;
    float s2 = s1 + (y4.y + y4.z) * halfdx;
    float s3 = s2 + (y4.z + y4.w) * halfdx;
    float tot = s3, v = tot;
#pragma unroll
    for (int o = 1; o < 32; o <<= 1) {
        float n = __shfl_up_sync(0xffffffffu, v, o);
        if (lane >= o) v += n;
    }
    __syncthreads();                 // protect wsum reuse across calls
    if (lane == 31) wsum[wi] = v;
    __syncthreads();
    float off = 0.f;
    for (int j = 0; j < wi; j++) off += wsum[j];
    float excl = off + v - tot;
    ph4[0] = TWO_PI_F * (excl + s0);
    ph4[1] = TWO_PI_F * (excl + s1);
    ph4[2] = TWO_PI_F * (excl + s2);
    ph4[3] = TWO_PI_F * (excl + s3);
}

// full-block reduce for u-projection
__device__ __forceinline__ float bred512(float v, volatile float* sred)
{
#pragma unroll
    for (int o = 16; o > 0; o >>= 1) v += __shfl_down_sync(0xffffffffu, v, o);
    __syncthreads();
    if ((threadIdx.x & 31) == 0) sred[threadIdx.x >> 5] = v;
    __syncthreads();
    float s = 0.f;
#pragma unroll
    for (int j = 0; j < 16; j++) s += sred[j];
    return s;
}

// ================= fused kernel: MLP + u + rhs + CG(x,y) + smooth CG =========
__global__ __launch_bounds__(NT) void fused_kernel(
    const float* __restrict__ s, const float* __restrict__ eIF,
    const float* __restrict__ xm, const float* __restrict__ ym,
    const float* __restrict__ sumx, const float* __restrict__ sumy,
    const float* __restrict__ lam, const int* __restrict__ mask,
    const float* __restrict__ initf,
    const float* __restrict__ alpha_p, const float* __restrict__ beta_p,
    const float* __restrict__ var_p, const float* __restrict__ fs_p,
    const int* __restrict__ iter_p,
    const float* __restrict__ fe_w1, const float* __restrict__ fe_b1,
    const float* __restrict__ fe_w2, const float* __restrict__ fe_b2,
    const float* __restrict__ pr_w1, const float* __restrict__ pr_b1,
    const float* __restrict__ pr_w2, const float* __restrict__ pr_b2,
    const float* __restrict__ pr_w3, const float* __restrict__ pr_b3,
    const float* __restrict__ iw_p,
    float* __restrict__ d_out)
{
    __shared__ float sp2[2][NN];
    __shared__ float sA2[2][16];
    __shared__ float sB2[2][16];
    __shared__ float wsum[16];
    __shared__ float m_avg[BB];
    __shared__ float m_h1[BB*32];
    __shared__ float m_z0[BB*18];
    __shared__ float m_z1[BB*64];
    __shared__ float m_z2[BB*32];
    __shared__ float m_res[BB*2];
    __shared__ float m_scal[4];

    const int bk = blockIdx.x;
    const int b = bk >> 2;
    const int tid = threadIdx.x;
    const float alpha = *alpha_p, beta = *beta_p;

    // ---------- MLP (recomputed per block; deterministic identical) ----------
    if (tid < BB) {
        const float* f = initf + tid * KK;
        m_avg[tid] = (((f[0] + f[1]) + f[2]) + f[3]) * 0.25f;
    }
    __syncthreads();
    if (tid < 256) {
        int bb = tid >> 5, j = tid & 31;
        m_h1[bb*32 + j] = fmaxf(0.f, m_avg[bb] * fe_w1[j] + fe_b1[j]);
    }
    __syncthreads();
    if (tid < 128) {
        int bb = tid >> 4, j = tid & 15;
        float acc = fe_b2[j];
        for (int e = 0; e < 32; e++) acc += m_h1[bb*32 + e] * fe_w2[j*32 + e];
        m_z0[bb*18 + j] = fmaxf(0.f, acc);
    }
    if (tid < BB) { m_z0[tid*18 + 16] = alpha; m_z0[tid*18 + 17] = beta; }
    __syncthreads();
    {
        int bb = tid >> 6, j = tid & 63;
        float acc = pr_b1[j];
        for (int e = 0; e < 18; e++) acc += m_z0[bb*18 + e] * pr_w1[j*18 + e];
        m_z1[bb*64 + j] = fmaxf(0.f, acc);
    }
    __syncthreads();
    if (tid < 256) {
        int bb = tid >> 5, j = tid & 31;
        float acc = pr_b2[j];
        for (int e = 0; e < 64; e++) acc += m_z1[bb*64 + e] * pr_w2[j*64 + e];
        m_z2[bb*32 + j] = fmaxf(0.f, acc);
    }
    __syncthreads();
    if (tid < 16) {
        int bb = tid >> 1, j = tid & 1;
        float acc = pr_b3[j];
        for (int e = 0; e < 32; e++) acc += m_z2[bb*32 + e] * pr_w3[j*32 + e];
        m_res[bb*2 + j] = tanhf(acc);
    }
    __syncthreads();
    if (tid == 0) {
        float iw = *iw_p;
        int it = *iter_p;
        float fac = 1.f / (1.f + expf(-iw * (float)it));
        float m0 = 0.f, m1 = 0.f;
        for (int bb = 0; bb < BB; bb++) {
            m0 += (m_res[bb*2 + 0] * fac * 0.1f) * alpha;
            m1 += (m_res[bb*2 + 1] * fac * 0.1f) * beta;
        }
        m0 *= 0.125f; m1 *= 0.125f;
        float na = fminf(fmaxf(alpha + m0, 1e-6f), 0.01f);
        float nb = fminf(fmaxf(beta  + m1, 1e-6f), 0.1f);
        double bt = pow(10.0, (double)it / 36.0 - 10.0);
        float betathr = fminf((float)bt, nb);
        m_scal[0] = na; m_scal[1] = nb;
        m_scal[2] = 2.f / na; m_scal[3] = 2.f / betathr;
        g_scal[0] = na; g_scal[1] = nb; g_scal[2] = m_scal[2]; g_scal[3] = m_scal[3];
        if (bk == 0) { d_out[OUT_SC + 0] = na; d_out[OUT_SC + 1] = nb; }
    }
    __syncthreads();
    const float na = m_scal[0];
    const float coefA = m_scal[2];
    const float coefS = m_scal[3];
    const float dxf = 1.0f / (*fs_p);
    const float halfdx = 0.5f * dxf;

    // ---------- u = projec5(...) over this batch row ----------
    const int base4 = tid * 4;
    const int bbase = b * NN + base4;
    float4 sv = *reinterpret_cast<const float4*>(s    + bbase);
    float4 sx = *reinterpret_cast<const float4*>(sumx + bbase);
    float4 sy = *reinterpret_cast<const float4*>(sumy + bbase);
    float4 lv = *reinterpret_cast<const float4*>(lam  + bbase);
    float uv[4];
    uv[0] = sv.x - sx.x - sy.x - lv.x / na;
    uv[1] = sv.y - sx.y - sy.y - lv.y / na;
    uv[2] = sv.z - sx.z - sy.z - lv.z / na;
    uv[3] = sv.w - sx.w - sy.w - lv.w / na;
    float loc = uv[0]*uv[0] + uv[1]*uv[1] + uv[2]*uv[2] + uv[3]*uv[3];
    float n2 = bred512(loc, sA2[0]);
    {
        float n = sqrtf(n2);
        float e = sqrtf((float)NN * (*var_p));
        float scale = (n > e) ? (e / fmaxf(n, 1e-30f)) : 1.f;
#pragma unroll
        for (int c = 0; c < 4; c++) { uv[c] *= scale; g_u[bbase + c] = uv[c]; }
    }

    // ---------- phase + rhs ----------
    float ph4[4];
    fast_phase(eIF + bk * NN, halfdx, wsum, ph4);
    const int rbase = bk * NN + base4;
#pragma unroll
    for (int c = 0; c < 4; c++) {
        float ssn, ccs;
        sincosf(ph4[c], &ssn, &ccs);
        float xv = xm[rbase + c], yv = ym[rbase + c];
        float resid = ((const float*)&sv.x)[c]
                    - (((const float*)&sx.x)[c] - xv * ccs)
                    - (((const float*)&sy.x)[c] - yv * ssn)
                    - uv[c]
                    - ((const float*)&lv.x)[c] / na;
        g_cos[rbase + c] = ccs;
        g_sin[rbase + c] = ssn;
        g_rhsx[rbase + c] = ccs * resid;
        g_rhsy[rbase + c] = ssn * resid;
    }
    __syncthreads();

    // ---------- concurrent CG for x (warps 0-7) and y (warps 8-15) ----------
    {
        const int grp = tid >> 8;          // 0 or 1
        const int gtid = tid & 255;
        const int barId = 1 + grp;
        const float* cs  = (grp ? g_sin  : g_cos)  + bk * NN;
        const float* rh  = (grp ? g_rhsy : g_rhsx) + bk * NN;
        const float* x0p = (grp ? ym     : xm)     + bk * NN;
        float*       outp = (grp ? g_ys  : g_xs)   + bk * NN;
        float* sp = sp2[grp];

        float d8[8], rhs8[8], x8[8];
#pragma unroll
        for (int c = 0; c < 8; c++) {
            int i = gtid * 8 + c;
            float cc = cs[i];
            d8[c] = cc * cc + 1e-6f;
            rhs8[c] = rh[i];
            x8[c] = x0p[i];
            sp[i] = x8[c];
        }
        cg_t<256, 8>(gtid, barId, coefA, d8, rhs8, x8, sp, sA2[grp], sB2[grp]);
#pragma unroll
        for (int c = 0; c < 8; c++) outp[gtid * 8 + c] = x8[c];
    }
    __syncthreads();

    // ---------- deltaIF + smooth CG (full block) ----------
    const float* xr = g_xs + bk * NN;
    const float* yr = g_ys + bk * NN;
    float rhs4[4], d4[4], x4[4];
#pragma unroll
    for (int c = 0; c < 4; c++) {
        int i = base4 + c;
        float xb, yb;
        if (i == 0) {
            xb = (xr[1] - xr[0]) / dxf;
            yb = (yr[1] - yr[0]) / dxf;
        } else if (i == NN - 1) {
            xb = (xr[NN-1] - xr[NN-2]) / dxf;
            yb = (yr[NN-1] - yr[NN-2]) / dxf;
        } else {
            xb = (xr[i+1] - xr[i-1]) / (2.0f * dxf);
            yb = (yr[i+1] - yr[i-1]) / (2.0f * dxf);
        }
        float xv = xr[i], yv = yr[i];
        float denom = xv * xv + yv * yv + 1e-12f;
        rhs4[c] = (xv * yb - yv * xb) / (denom * TWO_PI_F);
        d4[c] = 1.0f + 1e-6f;
        x4[c] = 0.f;
        sp2[0][i] = 0.f;
    }
    cg_t<512, 4>(tid, 0, coefS, d4, rhs4, x4, sp2[0], sA2[0], sB2[0]);

    // ---------- write eIF/xm/ym outputs ----------
    const bool act = (mask[bk] != 0);
#pragma unroll
    for (int c = 0; c < 4; c++) {
        int i = base4 + c;
        int gi = bk * NN + i;
        float e = eIF[gi];
        d_out[OUT_EIF + gi] = act ? (e - 0.5f * x4[c]) : e;
        d_out[OUT_XM  + gi] = act ? xr[i] : xm[gi];
        d_out[OUT_YM  + gi] = act ? yr[i] : ym[gi];
    }
}

// ================= final kernel: bsx/bsy + lamuda ============================
__global__ __launch_bounds__(NT) void final_kernel(const float* __restrict__ s,
                                                   const float* __restrict__ lam,
                                                   const int*   __restrict__ mask,
                                                   const float* __restrict__ fs_p,
                                                   float* __restrict__ d_out)
{
    __shared__ float wsum[16];
    int b = blockIdx.x;
    int tid = threadIdx.x;
    float na = g_scal[0];
    float halfdx = 0.5f / (*fs_p);

    float bsx[4] = {0.f, 0.f, 0.f, 0.f};
    float bsy[4] = {0.f, 0.f, 0.f, 0.f};

    for (int k = 0; k < KK; k++) {
        int bk = b * KK + k;
        const float* ne = d_out + OUT_EIF + bk * NN;
        float ph4[4];
        fast_phase(ne, halfdx, wsum, ph4);
        float mf = (mask[bk] != 0) ? 1.f : 0.f;
        int rbase = bk * NN + tid * 4;
#pragma unroll
        for (int c = 0; c < 4; c++) {
            float ssn, ccs;
            sincosf(ph4[c], &ssn, &ccs);
            bsx[c] += mf * d_out[OUT_XM + rbase + c] * ccs;
            bsy[c] += mf * d_out[OUT_YM + rbase + c] * ssn;
        }
    }
#pragma unroll
    for (int c = 0; c < 4; c++) {
        int i = tid * 4 + c;
        int gi = b * NN + i;
        d_out[OUT_BSX + gi] = bsx[c];
        d_out[OUT_BSY + gi] = bsy[c];
        d_out[OUT_LAM + gi] = lam[gi] + na * (g_u[gi] + bsx[c] + bsy[c] - s[gi]);
    }
}

// ---------------- launch ---------------------------------------------------
extern "C" void kernel_launch(void* const* d_in, const int* in_sizes, int n_in,
                              void* d_out_v, int out_size)
{
    const float* s      = (const float*)d_in[0];
    const float* eIF    = (const float*)d_in[1];
    const float* xm     = (const float*)d_in[2];
    const float* ym     = (const float*)d_in[3];
    const float* sum_x  = (const float*)d_in[4];
    const float* sum_y  = (const float*)d_in[5];
    const float* lamuda = (const float*)d_in[6];
    const float* initf  = (const float*)d_in[7];
    const int*   mmask  = (const int*)  d_in[8];
    const float* alpha  = (const float*)d_in[9];
    const float* beta   = (const float*)d_in[10];
    const float* var    = (const float*)d_in[11];
    const float* fs     = (const float*)d_in[12];
    const int*   iter   = (const int*)  d_in[13];
    const float* fe_w1  = (const float*)d_in[14];
    const float* fe_b1  = (const float*)d_in[15];
    const float* fe_w2  = (const float*)d_in[16];
    const float* fe_b2  = (const float*)d_in[17];
    const float* pr_w1  = (const float*)d_in[18];
    const float* pr_b1  = (const float*)d_in[19];
    const float* pr_w2  = (const float*)d_in[20];
    const float* pr_b2  = (const float*)d_in[21];
    const float* pr_w3  = (const float*)d_in[22];
    const float* pr_b3  = (const float*)d_in[23];
    const float* iw     = (const float*)d_in[24];
    float* d_out = (float*)d_out_v;

    fused_kernel<<<BK, NT>>>(s, eIF, xm, ym, sum_x, sum_y, lamuda, mmask,
                             initf, alpha, beta, var, fs, iter,
                             fe_w1, fe_b1, fe_w2, fe_b2,
                             pr_w1, pr_b1, pr_w2, pr_b2, pr_w3, pr_b3,
                             iw, d_out);
    final_kernel<<<BB, NT>>>(s, lamuda, mmask, fs, d_out);
}

// round 4
// speedup vs baseline: 2.4295x; 1.4442x over previous
#include <cuda_runtime.h>
#include <math.h>
#include <stdint.h>

// ---------------- problem constants ----------------
#define NN   2048
#define NT   512
#define BB   8
#define KK   4
#define BK   32
#define QN   (NN / KK)          // 512 elements per cluster-rank quarter
#define TWO_PI_F 6.283185307179586f

// output layout (flattened tuple, fp32)
#define OUT_EIF 0
#define OUT_XM  65536
#define OUT_YM  131072
#define OUT_BSX 196608
#define OUT_BSY 212992
#define OUT_LAM 229376
#define OUT_SC  245760

// ---------------- barrier helpers ----------------
template<int GSIZE>
__device__ __forceinline__ void barx(int barId)
{
    if (GSIZE == NT) __syncthreads();
    else asm volatile("bar.sync %0, %1;" :: "r"(barId), "r"(GSIZE) : "memory");
}

// single-value group reduce: shuffle chain -> partials -> one barrier -> all sum
template<int GSIZE>
__device__ __forceinline__ float gred1(float v, volatile float* sred, int gtid, int barId)
{
#pragma unroll
    for (int o = 16; o > 0; o >>= 1) v += __shfl_down_sync(0xffffffffu, v, o);
    if ((gtid & 31) == 0) sred[gtid >> 5] = v;
    barx<GSIZE>(barId);
    float s = 0.f;
#pragma unroll
    for (int j = 0; j < GSIZE / 32; j++) s += sred[j];
    return s;
}

// pentadiagonal stencil of (D^T D); window w[k] maps to element (base-2+k).
__device__ __forceinline__ float sten(const float* w, int c, int i)
{
    if (i == 0)        return 2.f*w[c+2] - 3.f*w[c+3] + w[c+4];
    if (i == 1)        return -3.f*w[c+1] + 6.f*w[c+2] - 4.f*w[c+3] + w[c+4];
    if (i == NN-2)     return w[c] - 4.f*w[c+1] + 6.f*w[c+2] - 3.f*w[c+3];
    if (i == NN-1)     return w[c] - 3.f*w[c+1] + 2.f*w[c+2];
    return w[c] - 4.f*w[c+1] + 6.f*w[c+2] - 4.f*w[c+3] + w[c+4];
}

// CG with reference semantics: explicit rsnew = ||r - a*Ap||^2 (computed from
// the actually-updated r), freeze == break (state frozen forever after done).
// p kept in registers; only r halo values (4 per thread) go through SMEM, and
// neighbor p halos are reconstructed as r_halo + beta * p_halo_old.
// sp points at element 0 of an [NN] view with 2 guard floats each side (guard
// VALUES are never used by the boundary stencil formulas).
// 2 barriers per iteration (the two reduction barriers).
template<int GSIZE, int NPT>
__device__ __forceinline__ void cg_solve(int gtid, int barId, float coef,
        const float* d, float* x, const float* rhs,
        float* sp, volatile float* sA, volatile float* sB, bool x0_zero)
{
    const int base = gtid * NPT;
    float r[NPT], p[NPT];
    float rl = 0.f;

    barx<GSIZE>(barId);                    // prior readers of sp region done
    if (x0_zero) {
#pragma unroll
        for (int c = 0; c < NPT; c++) { r[c] = rhs[c]; rl += r[c] * r[c]; }
    } else {
        sp[base] = x[0]; sp[base + 1] = x[1];
        sp[base + NPT - 2] = x[NPT - 2]; sp[base + NPT - 1] = x[NPT - 1];
        barx<GSIZE>(barId);
        float w[NPT + 4];
        w[0] = sp[base - 2]; w[1] = sp[base - 1];
        w[NPT + 2] = sp[base + NPT]; w[NPT + 3] = sp[base + NPT + 1];
#pragma unroll
        for (int c = 0; c < NPT; c++) w[c + 2] = x[c];
#pragma unroll
        for (int c = 0; c < NPT; c++) {
            float Ax = coef * sten(w, c, base + c) + d[c] * x[c];
            r[c] = rhs[c] - Ax;
            rl += r[c] * r[c];
        }
        barx<GSIZE>(barId);                // x-halo reads done before overwrite
    }
    // publish r halos (p = r initially), reduce rs
    sp[base] = r[0]; sp[base + 1] = r[1];
    sp[base + NPT - 2] = r[NPT - 2]; sp[base + NPT - 1] = r[NPT - 1];
    float rs = gred1<GSIZE>(rl, sB, gtid, barId);
    float hl0 = sp[base - 2], hl1 = sp[base - 1];
    float hr0 = sp[base + NPT], hr1 = sp[base + NPT + 1];
#pragma unroll
    for (int c = 0; c < NPT; c++) p[c] = r[c];

    for (int it = 0; it < 30; it++) {
        float w[NPT + 4];
        w[0] = hl0; w[1] = hl1; w[NPT + 2] = hr0; w[NPT + 3] = hr1;
#pragma unroll
        for (int c = 0; c < NPT; c++) w[c + 2] = p[c];
        float Ap[NPT];
        float pl = 0.f;
#pragma unroll
        for (int c = 0; c < NPT; c++) {
            Ap[c] = coef * sten(w, c, base + c) + d[c] * p[c];
            pl += p[c] * Ap[c];
        }
        float pAp = gred1<GSIZE>(pl, sA, gtid, barId);        // barrier 1
        float a = rs / (pAp + 1e-12f);
        float rl2 = 0.f;
#pragma unroll
        for (int c = 0; c < NPT; c++) {
            x[c] += a * p[c];
            r[c] -= a * Ap[c];
            rl2 += r[c] * r[c];
        }
        // publish new r halos before the rsnew barrier
        sp[base] = r[0]; sp[base + 1] = r[1];
        sp[base + NPT - 2] = r[NPT - 2]; sp[base + NPT - 1] = r[NPT - 1];
        float rsnew = gred1<GSIZE>(rl2, sB, gtid, barId);      // barrier 2
        if (sqrtf(rsnew) < 1e-6f) break;    // uniform across group; == freeze
        float bta = rsnew / (rs + 1e-12f);
        float nl0 = sp[base - 2], nl1 = sp[base - 1];
        float nr0 = sp[base + NPT], nr1 = sp[base + NPT + 1];
#pragma unroll
        for (int c = 0; c < NPT; c++) p[c] = r[c] + bta * p[c];
        hl0 = nl0 + bta * hl0; hl1 = nl1 + bta * hl1;
        hr0 = nr0 + bta * hr0; hr1 = nr1 + bta * hr1;
        rs = rsnew;
    }
}

// fast phase scan: full block, 4 contiguous elems/thread, y must be 16B aligned.
__device__ __forceinline__ void fast_phase(const float* __restrict__ y, float halfdx,
                                           volatile float* wsum, float ph4[4])
{
    int tid = threadIdx.x;
    int lane = tid & 31, wi = tid >> 5;
    int base = tid * 4;
    float4 y4 = *reinterpret_cast<const float4*>(y + base);
    float a0 = 0.f;
    if (base > 0) a0 = (y[base - 1] + y4.x) * halfdx;
    float s0 = a0;
    float s1 = s0 + (y4.x + y4.y) * halfdx;
    float s2 = s1 + (y4.y + y4.z) * halfdx;
    float s3 = s2 + (y4.z + y4.w) * halfdx;
    float tot = s3, v = tot;
#pragma unroll
    for (int o = 1; o < 32; o <<= 1) {
        float n = __shfl_up_sync(0xffffffffu, v, o);
        if (lane >= o) v += n;
    }
    __syncthreads();                 // protect wsum reuse + prior y stores read
    if (lane == 31) wsum[wi] = v;
    __syncthreads();
    float off = 0.f;
    for (int j = 0; j < wi; j++) off += wsum[j];
    float excl = off + v - tot;
    ph4[0] = TWO_PI_F * (excl + s0);
    ph4[1] = TWO_PI_F * (excl + s1);
    ph4[2] = TWO_PI_F * (excl + s2);
    ph4[3] = TWO_PI_F * (excl + s3);
}

// DSMEM scalar load from cluster rank `rk`
__device__ __forceinline__ float dsmem_ldf(const float* ptr, int rk)
{
    uint32_t a = (uint32_t)__cvta_generic_to_shared(ptr);
    uint32_t ra; float v;
    asm volatile("mapa.shared::cluster.u32 %0, %1, %2;" : "=r"(ra) : "r"(a), "r"(rk));
    asm volatile("ld.shared::cluster.f32 %0, [%1];" : "=f"(v) : "r"(ra) : "memory");
    return v;
}

// ================= ONE fused kernel (cluster of 4 CTAs = one batch) =========
__global__ __launch_bounds__(NT, 1) __cluster_dims__(KK, 1, 1)
void fused_kernel(
    const float* __restrict__ s_in, const float* __restrict__ eIF,
    const float* __restrict__ xm, const float* __restrict__ ym,
    const float* __restrict__ sumx, const float* __restrict__ sumy,
    const float* __restrict__ lam, const int* __restrict__ mask,
    const float* __restrict__ initf,
    const float* __restrict__ alpha_p, const float* __restrict__ beta_p,
    const float* __restrict__ var_p, const float* __restrict__ fs_p,
    const int* __restrict__ iter_p,
    const float* __restrict__ fe_w1, const float* __restrict__ fe_b1,
    const float* __restrict__ fe_w2, const float* __restrict__ fe_b2,
    const float* __restrict__ pr_w1, const float* __restrict__ pr_b1,
    const float* __restrict__ pr_w2, const float* __restrict__ pr_b2,
    const float* __restrict__ pr_w3, const float* __restrict__ pr_b3,
    const float* __restrict__ iw_p,
    float* __restrict__ d_out)
{
    // buffers (raw index [0,NN) at +0; CG p-views use +2 with 2 guards each side)
    __shared__ __align__(16) float sbuf0[NN + 4];  // cos -> sp_x -> sp_smooth -> cx
    __shared__ __align__(16) float sbuf1[NN + 4];  // sin -> sp_y -> newEIF -> cy
    __shared__ __align__(16) float brx[NN];        // rhsx -> xs
    __shared__ __align__(16) float bry[NN];        // rhsy -> ys
    __shared__ __align__(16) float u_buf[NN];
    __shared__ float sredA[2][16];
    __shared__ float sredB[2][16];
    __shared__ float wsum[16];
    __shared__ float m_avg[BB];
    __shared__ float m_h1[BB*32];
    __shared__ float m_z0[BB*18];
    __shared__ float m_z1[BB*64];
    __shared__ float m_z2[BB*32];
    __shared__ float m_res[BB*2];
    __shared__ float m_scal[4];

    const int bk  = blockIdx.x;
    const int b   = bk >> 2;
    const int rk  = bk & 3;          // cluster rank
    const int tid = threadIdx.x;
    const float alpha = *alpha_p, beta = *beta_p;

    // ---------- MLP (recomputed per CTA; identical everywhere) ----------
    if (tid < BB) {
        const float* f = initf + tid * KK;
        m_avg[tid] = (((f[0] + f[1]) + f[2]) + f[3]) * 0.25f;
    }
    __syncthreads();
    if (tid < 256) {
        int bb = tid >> 5, j = tid & 31;
        m_h1[bb*32 + j] = fmaxf(0.f, m_avg[bb] * fe_w1[j] + fe_b1[j]);
    }
    __syncthreads();
    if (tid < 128) {
        int bb = tid >> 4, j = tid & 15;
        float acc = fe_b2[j];
        for (int e = 0; e < 32; e++) acc += m_h1[bb*32 + e] * fe_w2[j*32 + e];
        m_z0[bb*18 + j] = fmaxf(0.f, acc);
    }
    if (tid < BB) { m_z0[tid*18 + 16] = alpha; m_z0[tid*18 + 17] = beta; }
    __syncthreads();
    {
        int bb = tid >> 6, j = tid & 63;
        float acc = pr_b1[j];
        for (int e = 0; e < 18; e++) acc += m_z0[bb*18 + e] * pr_w1[j*18 + e];
        m_z1[bb*64 + j] = fmaxf(0.f, acc);
    }
    __syncthreads();
    if (tid < 256) {
        int bb = tid >> 5, j = tid & 31;
        float acc = pr_b2[j];
        for (int e = 0; e < 64; e++) acc += m_z1[bb*64 + e] * pr_w2[j*64 + e];
        m_z2[bb*32 + j] = fmaxf(0.f, acc);
    }
    __syncthreads();
    if (tid < 16) {
        int bb = tid >> 1, j = tid & 1;
        float acc = pr_b3[j];
        for (int e = 0; e < 32; e++) acc += m_z2[bb*32 + e] * pr_w3[j*32 + e];
        m_res[bb*2 + j] = tanhf(acc);
    }
    __syncthreads();
    if (tid == 0) {
        float iw = *iw_p;
        int it = *iter_p;
        float fac = 1.f / (1.f + expf(-iw * (float)it));
        float m0 = 0.f, m1 = 0.f;
        for (int bb = 0; bb < BB; bb++) {
            m0 += (m_res[bb*2 + 0] * fac * 0.1f) * alpha;
            m1 += (m_res[bb*2 + 1] * fac * 0.1f) * beta;
        }
        m0 *= 0.125f; m1 *= 0.125f;
        float na = fminf(fmaxf(alpha + m0, 1e-6f), 0.01f);
        float nb = fminf(fmaxf(beta  + m1, 1e-6f), 0.1f);
        double bt = pow(10.0, (double)it / 36.0 - 10.0);
        float betathr = fminf((float)bt, nb);
        m_scal[0] = na; m_scal[1] = nb;
        m_scal[2] = 2.f / na; m_scal[3] = 2.f / betathr;
        if (bk == 0) { d_out[OUT_SC + 0] = na; d_out[OUT_SC + 1] = nb; }
    }
    __syncthreads();
    const float na = m_scal[0];
    const float coefA = m_scal[2];
    const float coefS = m_scal[3];
    const float dxf = 1.0f / (*fs_p);
    const float halfdx = 0.5f * dxf;

    // ---------- u = projec5(...) ----------
    const int base4 = tid * 4;
    const int bbase = b * NN + base4;
    float4 sv = *reinterpret_cast<const float4*>(s_in + bbase);
    float4 sx = *reinterpret_cast<const float4*>(sumx + bbase);
    float4 sy = *reinterpret_cast<const float4*>(sumy + bbase);
    float4 lv = *reinterpret_cast<const float4*>(lam  + bbase);
    float uv[4];
    uv[0] = sv.x - sx.x - sy.x - lv.x / na;
    uv[1] = sv.y - sx.y - sy.y - lv.y / na;
    uv[2] = sv.z - sx.z - sy.z - lv.z / na;
    uv[3] = sv.w - sx.w - sy.w - lv.w / na;
    {
        float loc = uv[0]*uv[0] + uv[1]*uv[1] + uv[2]*uv[2] + uv[3]*uv[3];
        float n2 = gred1<NT>(loc, sredA[0], tid, 0);
        float n = sqrtf(n2);
        float e = sqrtf((float)NN * (*var_p));
        float scale = (n > e) ? (e / fmaxf(n, 1e-30f)) : 1.f;
#pragma unroll
        for (int c = 0; c < 4; c++) { uv[c] *= scale; u_buf[base4 + c] = uv[c]; }
    }

    // ---------- phase + rhs (store to SMEM only) ----------
    {
        float ph4[4];
        fast_phase(eIF + bk * NN, halfdx, wsum, ph4);
        const int rbase = bk * NN + base4;
#pragma unroll
        for (int c = 0; c < 4; c++) {
            float ssn, ccs;
            sincosf(ph4[c], &ssn, &ccs);
            float xv = xm[rbase + c], yv = ym[rbase + c];
            float resid = ((const float*)&sv.x)[c]
                        - (((const float*)&sx.x)[c] - xv * ccs)
                        - (((const float*)&sy.x)[c] - yv * ssn)
                        - uv[c]
                        - ((const float*)&lv.x)[c] / na;
            sbuf0[base4 + c] = ccs;
            sbuf1[base4 + c] = ssn;
            brx[base4 + c] = ccs * resid;
            bry[base4 + c] = ssn * resid;
        }
    }
    __syncthreads();

    // ---------- concurrent CG for x (warps 0-7) and y (warps 8-15) ----------
    {
        const int grp = tid >> 8;
        const int gtid = tid & 255;
        const int barId = 1 + grp;
        const float* trig = grp ? sbuf1 : sbuf0;
        const float* rh   = grp ? bry   : brx;
        const float* x0g  = (grp ? ym : xm) + bk * NN;
        float* sp         = (grp ? sbuf1 : sbuf0) + 2;     // halo-exchange view
        float* outb       = grp ? bry : brx;

        float d8[8], rhs8[8], x8[8];
#pragma unroll
        for (int c = 0; c < 8; c++) {
            int i = gtid * 8 + c;
            float t = trig[i];
            d8[c] = t * t + 1e-6f;
            rhs8[c] = rh[i];
            x8[c] = x0g[i];
        }
        cg_solve<256, 8>(gtid, barId, coefA, d8, x8, rhs8, sp,
                         sredA[grp], sredB[grp], false);
        // write result over rhs buffer (only this group reads/writes it)
        barx<256>(barId);
#pragma unroll
        for (int c = 0; c < 8; c++) outb[gtid * 8 + c] = x8[c];
    }
    __syncthreads();

    // ---------- deltaIF + smooth CG ----------
    float xv4[4], yv4[4], x4[4];
    {
        float rhs4[4], d4[4];
#pragma unroll
        for (int c = 0; c < 4; c++) {
            int i = base4 + c;
            float xb, yb;
            if (i == 0) {
                xb = (brx[1] - brx[0]) / dxf;
                yb = (bry[1] - bry[0]) / dxf;
            } else if (i == NN - 1) {
                xb = (brx[NN-1] - brx[NN-2]) / dxf;
                yb = (bry[NN-1] - bry[NN-2]) / dxf;
            } else {
                xb = (brx[i+1] - brx[i-1]) / (2.0f * dxf);
                yb = (bry[i+1] - bry[i-1]) / (2.0f * dxf);
            }
            xv4[c] = brx[i]; yv4[c] = bry[i];
            float denom = xv4[c]*xv4[c] + yv4[c]*yv4[c] + 1e-12f;
            rhs4[c] = (xv4[c] * yb - yv4[c] * xb) / (denom * TWO_PI_F);
            d4[c] = 1.0f + 1e-6f;
            x4[c] = 0.f;
        }
        cg_solve<NT, 4>(tid, 0, coefS, d4, x4, rhs4, sbuf0 + 2,
                        sredA[0], sredB[0], true);
    }

    // ---------- outputs eIF/xm/ym + stash new_eIF for phase scan ----------
    const bool act = (mask[bk] != 0);
    float ne4[4];
#pragma unroll
    for (int c = 0; c < 4; c++) {
        int i = base4 + c;
        int gi = bk * NN + i;
        float e = eIF[gi];
        ne4[c] = act ? (e - 0.5f * x4[c]) : e;
        d_out[OUT_EIF + gi] = ne4[c];
        d_out[OUT_XM  + gi] = act ? xv4[c] : xm[gi];
        d_out[OUT_YM  + gi] = act ? yv4[c] : ym[gi];
        sbuf1[i] = ne4[c];
    }
    __syncthreads();

    // ---------- new phase + masked contributions into SMEM ----------
    {
        float ph4[4];
        fast_phase(sbuf1, halfdx, wsum, ph4);   // internal syncs make reads safe
        float cx[4], cy[4];
#pragma unroll
        for (int c = 0; c < 4; c++) {
            float ssn, ccs;
            sincosf(ph4[c], &ssn, &ccs);
            cx[c] = act ? xv4[c] * ccs : 0.f;
            cy[c] = act ? yv4[c] * ssn : 0.f;
        }
        __syncthreads();        // all fast_phase reads of sbuf1 complete
#pragma unroll
        for (int c = 0; c < 4; c++) {
            sbuf0[base4 + c] = cx[c];
            sbuf1[base4 + c] = cy[c];
        }
    }

    // ---------- cluster gather: bsx/bsy + lamuda ----------
    asm volatile("barrier.cluster.arrive.aligned;" ::: "memory");
    asm volatile("barrier.cluster.wait.aligned;"   ::: "memory");
    {
        int i = rk * QN + tid;
        float bsx = 0.f, bsy = 0.f;
#pragma unroll
        for (int k = 0; k < KK; k++) {
            bsx += dsmem_ldf(&sbuf0[i], k);
            bsy += dsmem_ldf(&sbuf1[i], k);
        }
        int gi = b * NN + i;
        d_out[OUT_BSX + gi] = bsx;
        d_out[OUT_BSY + gi] = bsy;
        d_out[OUT_LAM + gi] = lam[gi] + na * (u_buf[i] + bsx + bsy - s_in[gi]);
    }
    asm volatile("barrier.cluster.arrive.aligned;" ::: "memory");
    asm volatile("barrier.cluster.wait.aligned;"   ::: "memory");
}

// ---------------- launch ---------------------------------------------------
extern "C" void kernel_launch(void* const* d_in, const int* in_sizes, int n_in,
                              void* d_out_v, int out_size)
{
    const float* s      = (const float*)d_in[0];
    const float* eIF    = (const float*)d_in[1];
    const float* xm     = (const float*)d_in[2];
    const float* ym     = (const float*)d_in[3];
    const float* sum_x  = (const float*)d_in[4];
    const float* sum_y  = (const float*)d_in[5];
    const float* lamuda = (const float*)d_in[6];
    const float* initf  = (const float*)d_in[7];
    const int*   mmask  = (const int*)  d_in[8];
    const float* alpha  = (const float*)d_in[9];
    const float* beta   = (const float*)d_in[10];
    const float* var    = (const float*)d_in[11];
    const float* fs     = (const float*)d_in[12];
    const int*   iter   = (const int*)  d_in[13];
    const float* fe_w1  = (const float*)d_in[14];
    const float* fe_b1  = (const float*)d_in[15];
    const float* fe_w2  = (const float*)d_in[16];
    const float* fe_b2  = (const float*)d_in[17];
    const float* pr_w1  = (const float*)d_in[18];
    const float* pr_b1  = (const float*)d_in[19];
    const float* pr_w2  = (const float*)d_in[20];
    const float* pr_b2  = (const float*)d_in[21];
    const float* pr_w3  = (const float*)d_in[22];
    const float* pr_b3  = (const float*)d_in[23];
    const float* iw     = (const float*)d_in[24];
    float* d_out = (float*)d_out_v;

    fused_kernel<<<BK, NT>>>(s, eIF, xm, ym, sum_x, sum_y, lamuda, mmask,
                             initf, alpha, beta, var, fs, iter,
                             fe_w1, fe_b1, fe_w2, fe_b2,
                             pr_w1, pr_b1, pr_w2, pr_b2, pr_w3, pr_b3,
                             iw, d_out);
}